// round 4
// baseline (speedup 1.0000x reference)
#include <cuda_runtime.h>
#include <math.h>

#define Dd 256
#define Ss 128
#define Bb 64
#define G4 1024     // 4*D
#define JTOT 1280   // 4*D (gates) + D (enc_proj)
#define WQ_C 160    // Wq^T k-rows cached in smem

// ---------------- scratch (device globals; no allocation allowed) -------------
__device__ float g_WcatT[Dd * JTOT];     // [k][j] j<1024: W_ih^T ; j>=1024: We^T
__device__ float g_bcat[JTOT];           // b_ih+b_hh (j<1024) ; b1
__device__ float g_WhhT[Dd * G4];        // [k][j]
__device__ float g_WqT[Dd * Dd];         // [k][j]
__device__ float g_gpre[Bb * Ss * G4];   // W_ih@enc[b,s] + b_ih + b_hh
__device__ float g_eproj[Bb * Ss * Dd];  // enc@We^T + b1
__device__ float g_g0[Bb * G4];          // W_ih@dec_h0 + biases
__device__ float g_h0[Bb * Dd];          // mean over s of enc

// Accurate transcendentals built on MUFU.EX2/RCP; ~5e-7 abs err, safe for
// argmax decisions (tanh.approx's ~1e-3 err risks trajectory flips).
__device__ __forceinline__ float fsig(float x) {
    return __fdividef(1.f, 1.f + __expf(-x));
}
__device__ __forceinline__ float ftanh(float x) {
    return 1.f - __fdividef(2.f, __expf(2.f * x) + 1.f);
}

// ---------------- weight prep: transposes + bias folding ---------------------
__global__ void prep_k(const float* __restrict__ W_ih, const float* __restrict__ W_hh,
                       const float* __restrict__ b_ih, const float* __restrict__ b_hh,
                       const float* __restrict__ W1) {
    int i0 = blockIdx.x * blockDim.x + threadIdx.x;
    int stride = gridDim.x * blockDim.x;
    for (int idx = i0; idx < Dd * JTOT; idx += stride) {
        int k = idx / JTOT, j = idx - k * JTOT;
        g_WcatT[idx] = (j < G4) ? W_ih[j * Dd + k] : W1[(j - G4) * 512 + 256 + k];
    }
    for (int idx = i0; idx < Dd * G4; idx += stride) {
        int k = idx >> 10, j = idx & 1023;
        g_WhhT[idx] = W_hh[j * Dd + k];
    }
    for (int idx = i0; idx < Dd * Dd; idx += stride) {
        int k = idx >> 8, j = idx & 255;
        g_WqT[idx] = W1[j * 512 + k];
    }
}
__global__ void prepb_k(const float* __restrict__ b_ih, const float* __restrict__ b_hh,
                        const float* __restrict__ b1) {
    int i = blockIdx.x * blockDim.x + threadIdx.x;
    if (i < JTOT) g_bcat[i] = (i < G4) ? b_ih[i] + b_hh[i] : b1[i - G4];
}

// ---------------- dec_h0 = mean over s --------------------------------------
__global__ void mean_k(const float* __restrict__ enc) {
    int i = blockIdx.x * 256 + threadIdx.x;  // 16384 threads
    int b = i >> 8, d = i & 255;
    const float* p = enc + b * Ss * Dd + d;
    float s = 0.f;
#pragma unroll 8
    for (int t = 0; t < Ss; t++) s += p[t * Dd];
    g_h0[i] = s * (1.0f / 128.0f);
}

// ---------------- gates0 = dec_h0 @ W_ih^T + biases -------------------------
__global__ void __launch_bounds__(256) g0_k() {
    __shared__ float h[Dd];
    int b = blockIdx.x, t = threadIdx.x;
    h[t] = g_h0[b * Dd + t];
    __syncthreads();
    int j4 = t * 4;
    float4 acc = *(const float4*)&g_bcat[j4];
#pragma unroll 8
    for (int k = 0; k < Dd; k++) {
        float4 w = *(const float4*)&g_WcatT[k * JTOT + j4];
        float hk = h[k];
        acc.x = fmaf(w.x, hk, acc.x);
        acc.y = fmaf(w.y, hk, acc.y);
        acc.z = fmaf(w.z, hk, acc.z);
        acc.w = fmaf(w.w, hk, acc.w);
    }
    *(float4*)&g_g0[b * G4 + j4] = acc;
}

// ---------------- big precompute: gates_pre + enc_proj ----------------------
// grid (10, 64): blockIdx.x = J-tile (0..7 gates, 8..9 enc_proj), blockIdx.y = b
#define PRE_SMEM_FLOATS (32768 + 8192 + 128)
__global__ void __launch_bounds__(256) pre_k(const float* __restrict__ enc) {
    extern __shared__ float sm[];
    float* Wt = sm;                // [256][128]
    float* encs = sm + 32768;      // [32][256]
    float* bt = sm + 32768 + 8192; // [128]
    int b = blockIdx.y, jt = blockIdx.x, t = threadIdx.x;
    int J0 = jt * 128;
    for (int idx = t; idx < 32768; idx += 256) {
        int k = idx >> 7, jj = idx & 127;
        Wt[idx] = g_WcatT[k * JTOT + J0 + jj];
    }
    if (t < 128) bt[t] = g_bcat[J0 + t];
    int lane = t & 31, w = t >> 5;
    int j4 = lane * 4;
    int sb = w * 4;
    for (int pass = 0; pass < 4; pass++) {
        __syncthreads();
        for (int idx = t; idx < 32 * 256; idx += 256)
            encs[idx] = enc[b * Ss * Dd + pass * 32 * Dd + idx];
        __syncthreads();
        float4 bb = *(const float4*)&bt[j4];
        float4 a0 = bb, a1 = bb, a2 = bb, a3 = bb;
#pragma unroll 4
        for (int k = 0; k < Dd; k++) {
            float4 wv = *(const float4*)&Wt[k * 128 + j4];
            float e0 = encs[(sb + 0) * 256 + k];
            float e1 = encs[(sb + 1) * 256 + k];
            float e2 = encs[(sb + 2) * 256 + k];
            float e3 = encs[(sb + 3) * 256 + k];
            a0.x = fmaf(wv.x, e0, a0.x); a0.y = fmaf(wv.y, e0, a0.y);
            a0.z = fmaf(wv.z, e0, a0.z); a0.w = fmaf(wv.w, e0, a0.w);
            a1.x = fmaf(wv.x, e1, a1.x); a1.y = fmaf(wv.y, e1, a1.y);
            a1.z = fmaf(wv.z, e1, a1.z); a1.w = fmaf(wv.w, e1, a1.w);
            a2.x = fmaf(wv.x, e2, a2.x); a2.y = fmaf(wv.y, e2, a2.y);
            a2.z = fmaf(wv.z, e2, a2.z); a2.w = fmaf(wv.w, e2, a2.w);
            a3.x = fmaf(wv.x, e3, a3.x); a3.y = fmaf(wv.y, e3, a3.y);
            a3.z = fmaf(wv.z, e3, a3.z); a3.w = fmaf(wv.w, e3, a3.w);
        }
        int s0 = pass * 32 + sb;
        float4 as[4] = {a0, a1, a2, a3};
#pragma unroll
        for (int ss = 0; ss < 4; ss++) {
            int s = s0 + ss;
            if (jt < 8)
                *(float4*)&g_gpre[(b * Ss + s) * G4 + jt * 128 + j4] = as[ss];
            else
                *(float4*)&g_eproj[(b * Ss + s) * Dd + (jt - 8) * 128 + j4] = as[ss];
        }
    }
}

// ---------------- sequential decode: one CTA per 2 batches, 256 threads -----
// Key facts exploited:
//  * candidate set = next unscheduled op of each incomplete job (<=16 slots),
//    tracked by per-job counters next[16]; full 128-slot mask never needed.
//  * W_hh^T/Wq^T streamed once per step, FMA'd against TWO h vectors (batch
//    pairing halves chip L2 traffic; x2 keeps FMA-issue and L1TEX balanced).
//  * h for the two batches interleaved as float2 -> one broadcast LDS.64 per
//    k in the GEMV inner loops instead of two LDS.32.
//  * first WQ_C k-rows of Wq^T pinned in smem across all 128 steps.
#define DEC_SMEM_FLOATS (WQ_C * 256 + 2048 + 512 + 512 + 512 + 2048 + 32)
__global__ void __launch_bounds__(256) dec_k(const float* __restrict__ W2,
                                             const float* __restrict__ b2,
                                             float* __restrict__ out) {
    extern __shared__ float sm[];
    float* wqs   = sm;                  // [WQ_C][256]
    float* gat   = wqs + WQ_C * 256;    // [2][1024]
    float2* h2   = (float2*)(gat + 2048); // [256] (b0, b1) interleaved
    float* c_s   = gat + 2048 + 512;    // [2][256]
    float* q_s   = c_s + 512;           // [2][256]
    float* qpart = q_s + 512;           // [2][4][256]
    float* sc    = qpart + 2048;        // [2][16]
    __shared__ int next_s[2][16];       // ops scheduled per job
    __shared__ int chosen_sh[2];

    int bx = blockIdx.x, t = threadIdx.x;
    int lane = t & 31, w = t >> 5;
    int b0 = 2 * bx, b1 = 2 * bx + 1;

    for (int idx = t; idx < WQ_C * 256; idx += 256) wqs[idx] = g_WqT[idx];
    h2[t] = make_float2(0.f, 0.f);
    c_s[t] = 0.f; c_s[256 + t] = 0.f;
    if (t < 32) next_s[t >> 4][t & 15] = 0;

    // W2 is step-invariant: per-lane slice in registers (all warps need it)
    float4 w2a = *(const float4*)&W2[4 * lane];
    float4 w2b = *(const float4*)&W2[128 + 4 * lane];
    float b2v = b2[0];
    __syncthreads();

    for (int step = 0; step < Ss; step++) {
        // ---- phase 1: gates = gates_pre[dec_h] + h @ W_hh^T, both batches --
        {
            const float* gs0 = step ? &g_gpre[(b0 * Ss + chosen_sh[0]) * G4]
                                    : &g_g0[b0 * G4];
            const float* gs1 = step ? &g_gpre[(b1 * Ss + chosen_sh[1]) * G4]
                                    : &g_g0[b1 * G4];
            int j4 = t * 4;
            float4 a0 = *(const float4*)&gs0[j4];
            float4 a1 = *(const float4*)&gs1[j4];
#pragma unroll 8
            for (int k = 0; k < Dd; k++) {
                float4 wv = *(const float4*)&g_WhhT[k * G4 + j4];
                float2 hk = h2[k];  // broadcast LDS.64
                a0.x = fmaf(wv.x, hk.x, a0.x); a0.y = fmaf(wv.y, hk.x, a0.y);
                a0.z = fmaf(wv.z, hk.x, a0.z); a0.w = fmaf(wv.w, hk.x, a0.w);
                a1.x = fmaf(wv.x, hk.y, a1.x); a1.y = fmaf(wv.y, hk.y, a1.y);
                a1.z = fmaf(wv.z, hk.y, a1.z); a1.w = fmaf(wv.w, hk.y, a1.w);
            }
            *(float4*)&gat[j4] = a0;
            *(float4*)&gat[1024 + j4] = a1;
        }
        __syncthreads();

        // ---- phase 2: LSTM pointwise (thread t = feature d, both batches) --
        {
            float hn[2];
#pragma unroll
            for (int b = 0; b < 2; b++) {
                float ig = gat[b * 1024 + t], fg = gat[b * 1024 + 256 + t];
                float gg = gat[b * 1024 + 512 + t], og = gat[b * 1024 + 768 + t];
                float cn = fsig(fg) * c_s[b * 256 + t] + fsig(ig) * ftanh(gg);
                c_s[b * 256 + t] = cn;
                hn[b] = fsig(og) * ftanh(cn);
            }
            h2[t] = make_float2(hn[0], hn[1]);
        }
        __syncthreads();

        // ---- phase 3: q = h_new @ Wq^T (k split 4-way, both batches) ------
        {
            int jq = (t & 63) * 4, kq = t >> 6, k0 = kq * 64;
            float4 a0 = make_float4(0.f, 0.f, 0.f, 0.f);
            float4 a1 = make_float4(0.f, 0.f, 0.f, 0.f);
#pragma unroll 8
            for (int k = k0; k < k0 + 64; k++) {
                float4 wv = (k < WQ_C) ? *(const float4*)&wqs[k * Dd + jq]
                                       : *(const float4*)&g_WqT[k * Dd + jq];
                float2 hk = h2[k];
                a0.x = fmaf(wv.x, hk.x, a0.x); a0.y = fmaf(wv.y, hk.x, a0.y);
                a0.z = fmaf(wv.z, hk.x, a0.z); a0.w = fmaf(wv.w, hk.x, a0.w);
                a1.x = fmaf(wv.x, hk.y, a1.x); a1.y = fmaf(wv.y, hk.y, a1.y);
                a1.z = fmaf(wv.z, hk.y, a1.z); a1.w = fmaf(wv.w, hk.y, a1.w);
            }
            *(float4*)&qpart[kq * 256 + jq] = a0;
            *(float4*)&qpart[1024 + kq * 256 + jq] = a1;
        }
        __syncthreads();
        q_s[t] = qpart[t] + qpart[256 + t] + qpart[512 + t] + qpart[768 + t];
        q_s[256 + t] = qpart[1024 + t] + qpart[1280 + t] +
                       qpart[1536 + t] + qpart[1792 + t];
        __syncthreads();

        // ---- phase 4: attention scores, candidates only (<=16 per batch) --
        // warp w: batch = w>>2, jobs 4*(w&3)..+3; full warp per candidate row.
        {
            int b = w >> 2, jg = (w & 3) * 4;
            float4 qa = *(const float4*)&q_s[b * 256 + 4 * lane];
            float4 qb = *(const float4*)&q_s[b * 256 + 128 + 4 * lane];
            int bg = 2 * bx + b;
#pragma unroll
            for (int jj = 0; jj < 4; jj++) {
                int j = jg + jj;
                int nx = next_s[b][j];
                if (nx < 8) {  // warp-uniform branch
                    int s = j * 8 + nx;
                    const float* ep = &g_eproj[(bg * Ss + s) * Dd];
                    float4 ea = *(const float4*)&ep[4 * lane];
                    float4 eb = *(const float4*)&ep[128 + 4 * lane];
                    float v = w2a.x * ftanh(ea.x + qa.x) + w2a.y * ftanh(ea.y + qa.y) +
                              w2a.z * ftanh(ea.z + qa.z) + w2a.w * ftanh(ea.w + qa.w) +
                              w2b.x * ftanh(eb.x + qb.x) + w2b.y * ftanh(eb.y + qb.y) +
                              w2b.z * ftanh(eb.z + qb.z) + w2b.w * ftanh(eb.w + qb.w);
#pragma unroll
                    for (int off = 16; off; off >>= 1)
                        v += __shfl_xor_sync(0xffffffffu, v, off);
                    if (lane == 0) sc[b * 16 + j] = v + b2v;
                }
            }
        }
        __syncthreads();

        // ---- phase 5: argmax + log-sum-exp over candidates, update state --
        // Tie-break: reference argmax takes the lowest slot index; candidate
        // slot (j*8+next[j]) is monotone in j, so first-j-wins preserves it.
        if (t == 0 || t == 128) {
            int b = t >> 7;
            float best = -3.4e38f;
            int bj = 0;
            for (int j = 0; j < 16; j++) {
                if (next_s[b][j] < 8) {
                    float v = sc[b * 16 + j];
                    if (v > best) { best = v; bj = j; }
                }
            }
            float sum = 0.f;
            for (int j = 0; j < 16; j++)
                if (next_s[b][j] < 8) sum += __expf(sc[b * 16 + j] - best);
            int slot = bj * 8 + next_s[b][bj];
            int bg = 2 * bx + b;
            out[bg * Ss + step] = (float)slot;
            out[Bb * Ss + bg * Ss + step] = -__logf(sum);
            next_s[b][bj]++;
            chosen_sh[b] = slot;
        }
        __syncthreads();
    }
}

// ---------------- launcher ---------------------------------------------------
extern "C" void kernel_launch(void* const* d_in, const int* in_sizes, int n_in,
                              void* d_out, int out_size) {
    const float* enc  = (const float*)d_in[0];
    // d_in[1] = S_seq (deterministic job/op pattern, recomputed on device)
    const float* W_ih = (const float*)d_in[2];
    const float* W_hh = (const float*)d_in[3];
    const float* b_ih = (const float*)d_in[4];
    const float* b_hh = (const float*)d_in[5];
    const float* W1   = (const float*)d_in[6];
    const float* b1   = (const float*)d_in[7];
    const float* W2   = (const float*)d_in[8];
    const float* b2   = (const float*)d_in[9];
    float* out = (float*)d_out;

    cudaFuncSetAttribute(pre_k, cudaFuncAttributeMaxDynamicSharedMemorySize,
                         PRE_SMEM_FLOATS * 4);
    cudaFuncSetAttribute(dec_k, cudaFuncAttributeMaxDynamicSharedMemorySize,
                         DEC_SMEM_FLOATS * 4);

    prep_k<<<256, 256>>>(W_ih, W_hh, b_ih, b_hh, W1);
    prepb_k<<<8, 256>>>(b_ih, b_hh, b1);
    mean_k<<<64, 256>>>(enc);
    g0_k<<<64, 256>>>();
    pre_k<<<dim3(10, 64), 256, PRE_SMEM_FLOATS * 4>>>(enc);
    dec_k<<<32, 256, DEC_SMEM_FLOATS * 4>>>(W2, b2, out);
}

// round 7
// speedup vs baseline: 1.8513x; 1.8513x over previous
#include <cuda_runtime.h>
#include <math.h>
#include <stdint.h>

#define Dd 256
#define Ss 128
#define Bb 64
#define G4 1024     // 4*D
#define JTOT 1280   // 4*D (gates) + D (enc_proj)
#define WQ_C 160    // Wq^T k-rows cached in smem (multiple of 32!)

// ---------------- scratch (device globals; no allocation allowed) -------------
__device__ float g_WcatT[Dd * JTOT];     // [k][j] j<1024: W_ih^T ; j>=1024: We^T
__device__ float g_bcat[JTOT];           // b_ih+b_hh (j<1024) ; b1
__device__ float g_WhhT[Dd * G4];        // [k][j]
__device__ float g_WqT[Dd * Dd];         // [k][j]
__device__ float g_gpre[Bb * Ss * G4];   // W_ih@enc[b,s] + b_ih + b_hh
__device__ float g_eproj[Bb * Ss * Dd];  // enc@We^T + b1
__device__ float g_g0[Bb * G4];          // W_ih@dec_h0 + biases

// Accurate transcendentals built on MUFU.EX2/RCP; ~5e-7 abs err, safe for
// argmax decisions (tanh.approx's ~1e-3 err risks trajectory flips).
__device__ __forceinline__ float fsig(float x) {
    return __fdividef(1.f, 1.f + __expf(-x));
}
__device__ __forceinline__ float ftanh(float x) {
    return 1.f - __fdividef(2.f, __expf(2.f * x) + 1.f);
}

// ---- packed f32x2 helpers (Blackwell FFMA2; bit-exact IEEE fma per lane) ----
__device__ __forceinline__ uint64_t packsplat(float x) {
    uint64_t r;
    asm("mov.b64 %0, {%1, %1};" : "=l"(r) : "r"(__float_as_uint(x)));
    return r;
}
__device__ __forceinline__ uint64_t pack2(float lo, float hi) {
    uint64_t r;
    asm("mov.b64 %0, {%1, %2};" : "=l"(r) : "r"(__float_as_uint(lo)), "r"(__float_as_uint(hi)));
    return r;
}
__device__ __forceinline__ void ffma2(uint64_t& acc, uint64_t a, uint64_t b) {
    asm("fma.rn.f32x2 %0, %1, %2, %0;" : "+l"(acc) : "l"(a), "l"(b));
}

// ---------------- weight prep: transposes + bias folding ---------------------
__global__ void prep_k(const float* __restrict__ W_ih, const float* __restrict__ W_hh,
                       const float* __restrict__ b_ih, const float* __restrict__ b_hh,
                       const float* __restrict__ W1, const float* __restrict__ b1) {
    int i0 = blockIdx.x * blockDim.x + threadIdx.x;
    int stride = gridDim.x * blockDim.x;
    for (int idx = i0; idx < Dd * JTOT; idx += stride) {
        int k = idx / JTOT, j = idx - k * JTOT;
        g_WcatT[idx] = (j < G4) ? W_ih[j * Dd + k] : W1[(j - G4) * 512 + 256 + k];
    }
    for (int idx = i0; idx < Dd * G4; idx += stride) {
        int k = idx >> 10, j = idx & 1023;
        g_WhhT[idx] = W_hh[j * Dd + k];
    }
    for (int idx = i0; idx < Dd * Dd; idx += stride) {
        int k = idx >> 8, j = idx & 255;
        g_WqT[idx] = W1[j * 512 + k];
    }
    if (i0 < JTOT) g_bcat[i0] = (i0 < G4) ? b_ih[i0] + b_hh[i0] : b1[i0 - G4];
}

// ------- dec_h0 = mean over s, then gates0 = dec_h0 @ W_ih^T + biases -------
__global__ void __launch_bounds__(256) g0m_k(const float* __restrict__ enc) {
    __shared__ float h[Dd];
    int b = blockIdx.x, t = threadIdx.x;
    {
        const float* p = enc + b * Ss * Dd + t;
        float s = 0.f;
#pragma unroll 8
        for (int ss = 0; ss < Ss; ss++) s += p[ss * Dd];
        h[t] = s * (1.0f / 128.0f);
    }
    __syncthreads();
    int j4 = t * 4;
    float4 acc = *(const float4*)&g_bcat[j4];
#pragma unroll 8
    for (int k = 0; k < Dd; k++) {
        float4 w = *(const float4*)&g_WcatT[k * JTOT + j4];
        float hk = h[k];
        acc.x = fmaf(w.x, hk, acc.x);
        acc.y = fmaf(w.y, hk, acc.y);
        acc.z = fmaf(w.z, hk, acc.z);
        acc.w = fmaf(w.w, hk, acc.w);
    }
    *(float4*)&g_g0[b * G4 + j4] = acc;
}

// ---------------- big precompute: gates_pre + enc_proj ----------------------
// grid (10, 64): blockIdx.x = J-tile (0..7 gates, 8..9 enc_proj), blockIdx.y = b
#define PRE_SMEM_FLOATS (32768 + 8192 + 128)
__global__ void __launch_bounds__(256) pre_k(const float* __restrict__ enc) {
    extern __shared__ float sm[];
    float* Wt = sm;                // [256][128]
    float* encs = sm + 32768;      // [32][256]
    float* bt = sm + 32768 + 8192; // [128]
    int b = blockIdx.y, jt = blockIdx.x, t = threadIdx.x;
    int J0 = jt * 128;
    for (int idx = t; idx < 32768; idx += 256) {
        int k = idx >> 7, jj = idx & 127;
        Wt[idx] = g_WcatT[k * JTOT + J0 + jj];
    }
    if (t < 128) bt[t] = g_bcat[J0 + t];
    int lane = t & 31, w = t >> 5;
    int j4 = lane * 4;
    int sb = w * 4;
    for (int pass = 0; pass < 4; pass++) {
        __syncthreads();
        for (int idx = t; idx < 32 * 256; idx += 256)
            encs[idx] = enc[b * Ss * Dd + pass * 32 * Dd + idx];
        __syncthreads();
        float4 bb = *(const float4*)&bt[j4];
        float4 a0 = bb, a1 = bb, a2 = bb, a3 = bb;
#pragma unroll 4
        for (int k = 0; k < Dd; k++) {
            float4 wv = *(const float4*)&Wt[k * 128 + j4];
            float e0 = encs[(sb + 0) * 256 + k];
            float e1 = encs[(sb + 1) * 256 + k];
            float e2 = encs[(sb + 2) * 256 + k];
            float e3 = encs[(sb + 3) * 256 + k];
            a0.x = fmaf(wv.x, e0, a0.x); a0.y = fmaf(wv.y, e0, a0.y);
            a0.z = fmaf(wv.z, e0, a0.z); a0.w = fmaf(wv.w, e0, a0.w);
            a1.x = fmaf(wv.x, e1, a1.x); a1.y = fmaf(wv.y, e1, a1.y);
            a1.z = fmaf(wv.z, e1, a1.z); a1.w = fmaf(wv.w, e1, a1.w);
            a2.x = fmaf(wv.x, e2, a2.x); a2.y = fmaf(wv.y, e2, a2.y);
            a2.z = fmaf(wv.z, e2, a2.z); a2.w = fmaf(wv.w, e2, a2.w);
            a3.x = fmaf(wv.x, e3, a3.x); a3.y = fmaf(wv.y, e3, a3.y);
            a3.z = fmaf(wv.z, e3, a3.z); a3.w = fmaf(wv.w, e3, a3.w);
        }
        int s0 = pass * 32 + sb;
        float4 as[4] = {a0, a1, a2, a3};
#pragma unroll
        for (int ss = 0; ss < 4; ss++) {
            int s = s0 + ss;
            if (jt < 8)
                *(float4*)&g_gpre[(b * Ss + s) * G4 + jt * 128 + j4] = as[ss];
            else  // jt in {8,9} -> row halves at offsets 0 / 128 within Dd=256
                *(float4*)&g_eproj[(b * Ss + s) * Dd + (jt - 8) * 128 + j4] = as[ss];
        }
    }
}

// ---------------- sequential decode: one CTA per 2 batches, 512 threads -----
//  * candidate set = next unscheduled op of each incomplete job (<=16 slots).
//  * W_hh^T/Wq^T streamed once per step, FMA'd against TWO h vectors.
//  * 512 threads with k-split GEMVs (phase1 2-way, phase3 8-way) for latency
//    hiding; partials reduced through smem scratch.
//  * phase 1 uses packed fma.rn.f32x2 (j-pair packing) -> 25% less FMA issue.
//  * first WQ_C k-rows of Wq^T pinned in smem; 32-k split blocks make the
//    smem/global choice warp-uniform and hoistable.
#define DEC_SMEM_FLOATS (WQ_C * 256 + 2048 + 512 + 512 + 512 + 4096 + 32)
__global__ void __launch_bounds__(512) dec_k(const float* __restrict__ W2,
                                             const float* __restrict__ b2,
                                             float* __restrict__ out) {
    extern __shared__ float sm[];
    float* wqs   = sm;                    // [WQ_C][256]
    float* gat   = wqs + WQ_C * 256;      // [2][1024]
    float* h2f   = gat + 2048;            // [256][2] interleaved (b0,b1)
    float* c_s   = h2f + 512;             // [2][256]
    float* q_s   = c_s + 512;             // [2][256]
    float* scr   = q_s + 512;             // 4096 scratch (phase1 & phase3 partials)
    float* sc    = scr + 4096;            // [2][16]
    __shared__ int next_s[2][16];         // ops scheduled per job
    __shared__ int chosen_sh[2];

    int bx = blockIdx.x, t = threadIdx.x;
    int lane = t & 31, w = t >> 5;
    int b0 = 2 * bx, b1 = 2 * bx + 1;
    const float2* h2 = (const float2*)h2f;

    for (int idx = t; idx < WQ_C * 256; idx += 512) wqs[idx] = g_WqT[idx];
    h2f[t] = 0.f;
    if (t < 256) { c_s[t] = 0.f; c_s[256 + t] = 0.f; }
    if (t < 32) next_s[t >> 4][t & 15] = 0;

    float4 w2a = *(const float4*)&W2[4 * lane];
    float4 w2b = *(const float4*)&W2[128 + 4 * lane];
    float b2v = b2[0];
    __syncthreads();

    for (int step = 0; step < Ss; step++) {
        // ---- phase 1: gates = gates_pre[dec_h] + h @ W_hh^T (k-split x2) ---
        {
            int j4 = (t & 255) * 4, kh = t >> 8;   // kh in {0,1}: k-half
            uint64_t ac0, ac1, ac2, ac3;           // (j,j+1)/(j+2,j+3) x b0,b1
            if (kh == 0) {
                const float* gs0 = step ? &g_gpre[(b0 * Ss + chosen_sh[0]) * G4]
                                        : &g_g0[b0 * G4];
                const float* gs1 = step ? &g_gpre[(b1 * Ss + chosen_sh[1]) * G4]
                                        : &g_g0[b1 * G4];
                float4 i0 = *(const float4*)&gs0[j4];
                float4 i1 = *(const float4*)&gs1[j4];
                ac0 = pack2(i0.x, i0.y); ac1 = pack2(i0.z, i0.w);
                ac2 = pack2(i1.x, i1.y); ac3 = pack2(i1.z, i1.w);
            } else {
                ac0 = ac1 = ac2 = ac3 = 0ull;
            }
            int k0 = kh * 128;
#pragma unroll 8
            for (int k = k0; k < k0 + 128; k++) {
                ulonglong2 wv = *(const ulonglong2*)&g_WhhT[k * G4 + j4];
                float2 hk = h2[k];                 // broadcast LDS.64
                uint64_t hx = packsplat(hk.x), hy = packsplat(hk.y);
                ffma2(ac0, wv.x, hx); ffma2(ac1, wv.y, hx);
                ffma2(ac2, wv.x, hy); ffma2(ac3, wv.y, hy);
            }
            ulonglong2* dst0 = (ulonglong2*)&scr[kh * 2048 + j4];
            ulonglong2* dst1 = (ulonglong2*)&scr[kh * 2048 + 1024 + j4];
            dst0->x = ac0; dst0->y = ac1;
            dst1->x = ac2; dst1->y = ac3;
        }
        __syncthreads();
        // reduce k-halves: scr layout [kh][b][1024]
        {
            gat[t] = scr[t] + scr[2048 + t];
            gat[512 + t] = scr[512 + t] + scr[2560 + t];
            gat[1024 + t] = scr[1024 + t] + scr[3072 + t];
            gat[1536 + t] = scr[1536 + t] + scr[3584 + t];
        }
        __syncthreads();

        // ---- phase 2: LSTM pointwise (b = t>>8, d = t&255) -----------------
        {
            int b = t >> 8, d = t & 255;
            float ig = gat[b * 1024 + d], fg = gat[b * 1024 + 256 + d];
            float gg = gat[b * 1024 + 512 + d], og = gat[b * 1024 + 768 + d];
            float cn = fsig(fg) * c_s[b * 256 + d] + fsig(ig) * ftanh(gg);
            c_s[b * 256 + d] = cn;
            h2f[2 * d + b] = fsig(og) * ftanh(cn);
        }
        __syncthreads();

        // ---- phase 3: q = h_new @ Wq^T (k-split x8, both batches) ----------
        {
            int jq = (t & 63) * 4, kq = t >> 6, k0 = kq * 32;
            float4 a0 = make_float4(0.f, 0.f, 0.f, 0.f);
            float4 a1 = make_float4(0.f, 0.f, 0.f, 0.f);
            const float* base = (k0 < WQ_C) ? wqs : g_WqT;  // warp-uniform
#pragma unroll 8
            for (int k = k0; k < k0 + 32; k++) {
                float4 wv = *(const float4*)&base[k * Dd + jq];
                float2 hk = h2[k];
                a0.x = fmaf(wv.x, hk.x, a0.x); a0.y = fmaf(wv.y, hk.x, a0.y);
                a0.z = fmaf(wv.z, hk.x, a0.z); a0.w = fmaf(wv.w, hk.x, a0.w);
                a1.x = fmaf(wv.x, hk.y, a1.x); a1.y = fmaf(wv.y, hk.y, a1.y);
                a1.z = fmaf(wv.z, hk.y, a1.z); a1.w = fmaf(wv.w, hk.y, a1.w);
            }
            *(float4*)&scr[kq * 512 + jq] = a0;
            *(float4*)&scr[kq * 512 + 256 + jq] = a1;
        }
        __syncthreads();
        {
            int b = t >> 8, d = t & 255;
            float s = 0.f;
#pragma unroll
            for (int kq = 0; kq < 8; kq++) s += scr[kq * 512 + b * 256 + d];
            q_s[b * 256 + d] = s;
        }
        __syncthreads();

        // ---- phase 4: attention, candidates only (warp w: b=w>>3, 2 jobs) -
        {
            int b = w >> 3, jg = (w & 7) * 2;
            float4 qa = *(const float4*)&q_s[b * 256 + 4 * lane];
            float4 qb = *(const float4*)&q_s[b * 256 + 128 + 4 * lane];
            int bg = 2 * bx + b;
#pragma unroll
            for (int jj = 0; jj < 2; jj++) {
                int j = jg + jj;
                int nx = next_s[b][j];
                if (nx < 8) {  // warp-uniform branch
                    int s = j * 8 + nx;
                    const float* ep = &g_eproj[(bg * Ss + s) * Dd];
                    float4 ea = *(const float4*)&ep[4 * lane];
                    float4 eb = *(const float4*)&ep[128 + 4 * lane];
                    float v = w2a.x * ftanh(ea.x + qa.x) + w2a.y * ftanh(ea.y + qa.y) +
                              w2a.z * ftanh(ea.z + qa.z) + w2a.w * ftanh(ea.w + qa.w) +
                              w2b.x * ftanh(eb.x + qb.x) + w2b.y * ftanh(eb.y + qb.y) +
                              w2b.z * ftanh(eb.z + qb.z) + w2b.w * ftanh(eb.w + qb.w);
#pragma unroll
                    for (int off = 16; off; off >>= 1)
                        v += __shfl_xor_sync(0xffffffffu, v, off);
                    if (lane == 0) sc[b * 16 + j] = v + b2v;
                }
            }
        }
        __syncthreads();

        // ---- phase 5: argmax + lse over candidates, update state -----------
        // Reference tie-break = lowest slot index; candidate slot j*8+next[j]
        // is monotone in j, so first-j-wins preserves it.
        if (t == 0 || t == 256) {
            int b = t >> 8;
            float best = -3.4e38f;
            int bj = 0;
            for (int j = 0; j < 16; j++) {
                if (next_s[b][j] < 8) {
                    float v = sc[b * 16 + j];
                    if (v > best) { best = v; bj = j; }
                }
            }
            float sum = 0.f;
            for (int j = 0; j < 16; j++)
                if (next_s[b][j] < 8) sum += __expf(sc[b * 16 + j] - best);
            int slot = bj * 8 + next_s[b][bj];
            int bg = 2 * bx + b;
            out[bg * Ss + step] = (float)slot;
            out[Bb * Ss + bg * Ss + step] = -__logf(sum);
            next_s[b][bj]++;
            chosen_sh[b] = slot;
        }
        __syncthreads();
    }
}

// ---------------- launcher ---------------------------------------------------
extern "C" void kernel_launch(void* const* d_in, const int* in_sizes, int n_in,
                              void* d_out, int out_size) {
    const float* enc  = (const float*)d_in[0];
    // d_in[1] = S_seq (deterministic job/op pattern, recomputed on device)
    const float* W_ih = (const float*)d_in[2];
    const float* W_hh = (const float*)d_in[3];
    const float* b_ih = (const float*)d_in[4];
    const float* b_hh = (const float*)d_in[5];
    const float* W1   = (const float*)d_in[6];
    const float* b1   = (const float*)d_in[7];
    const float* W2   = (const float*)d_in[8];
    const float* b2   = (const float*)d_in[9];
    float* out = (float*)d_out;

    cudaFuncSetAttribute(pre_k, cudaFuncAttributeMaxDynamicSharedMemorySize,
                         PRE_SMEM_FLOATS * 4);
    cudaFuncSetAttribute(dec_k, cudaFuncAttributeMaxDynamicSharedMemorySize,
                         DEC_SMEM_FLOATS * 4);

    prep_k<<<256, 256>>>(W_ih, W_hh, b_ih, b_hh, W1, b1);
    g0m_k<<<64, 256>>>(enc);
    pre_k<<<dim3(10, 64), 256, PRE_SMEM_FLOATS * 4>>>(enc);
    dec_k<<<32, 512, DEC_SMEM_FLOATS * 4>>>(W2, b2, out);
}

// round 14
// speedup vs baseline: 2.5716x; 1.3891x over previous
#include <cuda_runtime.h>
#include <math.h>
#include <stdint.h>

#define Dd 256
#define Ss 128
#define Bb 64
#define G4 1024     // 4*D
#define JTOT 1280   // 4*D (gates) + D (enc_proj)
#define CLU 8       // cluster size = ranks per cluster = batches per cluster

// ---------------- scratch (device globals; no allocation allowed) -------------
__device__ float g_WcatT[Dd * JTOT];     // [k][j] j<1024: W_ih^T (PERMUTED cols); j>=1024: We^T
__device__ float g_bcat[JTOT];           // b_ih+b_hh (PERMUTED, j<1024) ; b1
__device__ float g_WhhT[Dd * G4];        // [k][j PERMUTED]
__device__ float g_WqT[Dd * Dd];         // [k][j] natural order
__device__ float g_gpre[Bb * Ss * G4];   // permuted-j gate premix
__device__ float g_eproj[Bb * Ss * Dd];  // enc@We^T + b1 (natural d order)
__device__ float g_g0[Bb * G4];          // permuted-j gates for dec_h0

// Gate-column permutation: global gate row j = g*256 + d (g=gate id, d=dim).
// pos(j) = r*128 + g*32 + jj with r = d>>5, jj = d&31  ->  rank r owns a
// contiguous 128-wide slice covering dims d in [r*32, r*32+32) for all four
// gates, so the LSTM pointwise is rank-local.
__device__ __forceinline__ int permj(int j) {
    int g = j >> 8, d = j & 255;
    return ((d >> 5) << 7) + (g << 5) + (d & 31);
}

// Accurate transcendentals (MUFU.EX2/RCP based, ~5e-7 abs err).
__device__ __forceinline__ float fsig(float x) {
    return __fdividef(1.f, 1.f + __expf(-x));
}
__device__ __forceinline__ float ftanh(float x) {
    return 1.f - __fdividef(2.f, __expf(2.f * x) + 1.f);
}

// ---- packed f32x2 helpers (bit-exact IEEE fma per lane) ----
__device__ __forceinline__ uint64_t packsplat(float x) {
    uint64_t r;
    asm("mov.b64 %0, {%1, %1};" : "=l"(r) : "r"(__float_as_uint(x)));
    return r;
}
__device__ __forceinline__ void ffma2(uint64_t& acc, uint64_t a, uint64_t b) {
    asm("fma.rn.f32x2 %0, %1, %2, %0;" : "+l"(acc) : "l"(a), "l"(b));
}
__device__ __forceinline__ float lo2(uint64_t v) { return __uint_as_float((uint32_t)v); }
__device__ __forceinline__ float hi2(uint64_t v) { return __uint_as_float((uint32_t)(v >> 32)); }

// ---- cluster / DSMEM helpers ----
__device__ __forceinline__ uint32_t smem_u32(const void* p) {
    uint32_t a;
    asm("{ .reg .u64 t; cvta.to.shared.u64 t, %1; cvt.u32.u64 %0, t; }" : "=r"(a) : "l"(p));
    return a;
}
__device__ __forceinline__ uint32_t ctarank() {
    uint32_t r; asm("mov.u32 %0, %%cluster_ctarank;" : "=r"(r)); return r;
}
__device__ __forceinline__ uint32_t mapa_u32(uint32_t local, uint32_t rank) {
    uint32_t r; asm("mapa.shared::cluster.u32 %0, %1, %2;" : "=r"(r) : "r"(local), "r"(rank));
    return r;
}
__device__ __forceinline__ void stc_f4(uint32_t a, float4 v) {
    asm volatile("st.shared::cluster.v4.f32 [%0], {%1,%2,%3,%4};"
                 :: "r"(a), "f"(v.x), "f"(v.y), "f"(v.z), "f"(v.w) : "memory");
}
__device__ __forceinline__ void stc_f(uint32_t a, float v) {
    asm volatile("st.shared::cluster.f32 [%0], %1;" :: "r"(a), "f"(v) : "memory");
}
__device__ __forceinline__ int ldc_s32(uint32_t a) {
    int v; asm volatile("ld.shared::cluster.b32 %0, [%1];" : "=r"(v) : "r"(a) : "memory");
    return v;
}
__device__ __forceinline__ void prefetch_l2(const void* p) {
    asm volatile("prefetch.global.L2 [%0];" :: "l"(p));
}
#define CLUSTER_SYNC() do { \
    asm volatile("barrier.cluster.arrive.aligned;" ::: "memory"); \
    asm volatile("barrier.cluster.wait.aligned;" ::: "memory"); \
} while (0)

// ---------------- weight prep: transposes + permutation + bias folding -------
__global__ void prep_k(const float* __restrict__ W_ih, const float* __restrict__ W_hh,
                       const float* __restrict__ b_ih, const float* __restrict__ b_hh,
                       const float* __restrict__ W1, const float* __restrict__ b1) {
    int i0 = blockIdx.x * blockDim.x + threadIdx.x;
    int stride = gridDim.x * blockDim.x;
    for (int idx = i0; idx < Dd * JTOT; idx += stride) {
        int k = idx / JTOT, j = idx - k * JTOT;
        if (j < G4)
            g_WcatT[k * JTOT + permj(j)] = W_ih[j * Dd + k];
        else
            g_WcatT[idx] = W1[(j - G4) * 512 + 256 + k];
    }
    for (int idx = i0; idx < Dd * G4; idx += stride) {
        int k = idx >> 10, j = idx & 1023;
        g_WhhT[k * G4 + permj(j)] = W_hh[j * Dd + k];
    }
    for (int idx = i0; idx < Dd * Dd; idx += stride) {
        int k = idx >> 8, j = idx & 255;
        g_WqT[idx] = W1[j * 512 + k];
    }
    if (i0 < JTOT) {
        float v = (i0 < G4) ? b_ih[i0] + b_hh[i0] : b1[i0 - G4];
        g_bcat[(i0 < G4) ? permj(i0) : i0] = v;
    }
}

// ------- dec_h0 = mean over s, then gates0 = dec_h0 @ W_ih^T + biases -------
__global__ void __launch_bounds__(256) g0m_k(const float* __restrict__ enc) {
    __shared__ float h[Dd];
    int b = blockIdx.x, t = threadIdx.x;
    {
        const float* p = enc + b * Ss * Dd + t;
        float s = 0.f;
#pragma unroll 8
        for (int ss = 0; ss < Ss; ss++) s += p[ss * Dd];
        h[t] = s * (1.0f / 128.0f);
    }
    __syncthreads();
    int j4 = t * 4;
    float4 acc = *(const float4*)&g_bcat[j4];
#pragma unroll 8
    for (int k = 0; k < Dd; k++) {
        float4 w = *(const float4*)&g_WcatT[k * JTOT + j4];
        float hk = h[k];
        acc.x = fmaf(w.x, hk, acc.x);
        acc.y = fmaf(w.y, hk, acc.y);
        acc.z = fmaf(w.z, hk, acc.z);
        acc.w = fmaf(w.w, hk, acc.w);
    }
    *(float4*)&g_g0[b * G4 + j4] = acc;
}

// ---------------- big precompute: gates_pre (permuted) + enc_proj -----------
#define PRE_SMEM_FLOATS (32768 + 8192 + 128)
__global__ void __launch_bounds__(256) pre_k(const float* __restrict__ enc) {
    extern __shared__ float sm[];
    float* Wt = sm;                // [256][128]
    float* encs = sm + 32768;      // [32][256]
    float* bt = sm + 32768 + 8192; // [128]
    int b = blockIdx.y, jt = blockIdx.x, t = threadIdx.x;
    int J0 = jt * 128;
    for (int idx = t; idx < 32768; idx += 256) {
        int k = idx >> 7, jj = idx & 127;
        Wt[idx] = g_WcatT[k * JTOT + J0 + jj];
    }
    if (t < 128) bt[t] = g_bcat[J0 + t];
    int lane = t & 31, w = t >> 5;
    int j4 = lane * 4;
    int sb = w * 4;
    for (int pass = 0; pass < 4; pass++) {
        __syncthreads();
        for (int idx = t; idx < 32 * 256; idx += 256)
            encs[idx] = enc[b * Ss * Dd + pass * 32 * Dd + idx];
        __syncthreads();
        float4 bb = *(const float4*)&bt[j4];
        float4 a0 = bb, a1 = bb, a2 = bb, a3 = bb;
#pragma unroll 4
        for (int k = 0; k < Dd; k++) {
            float4 wv = *(const float4*)&Wt[k * 128 + j4];
            float e0 = encs[(sb + 0) * 256 + k];
            float e1 = encs[(sb + 1) * 256 + k];
            float e2 = encs[(sb + 2) * 256 + k];
            float e3 = encs[(sb + 3) * 256 + k];
            a0.x = fmaf(wv.x, e0, a0.x); a0.y = fmaf(wv.y, e0, a0.y);
            a0.z = fmaf(wv.z, e0, a0.z); a0.w = fmaf(wv.w, e0, a0.w);
            a1.x = fmaf(wv.x, e1, a1.x); a1.y = fmaf(wv.y, e1, a1.y);
            a1.z = fmaf(wv.z, e1, a1.z); a1.w = fmaf(wv.w, e1, a1.w);
            a2.x = fmaf(wv.x, e2, a2.x); a2.y = fmaf(wv.y, e2, a2.y);
            a2.z = fmaf(wv.z, e2, a2.z); a2.w = fmaf(wv.w, e2, a2.w);
            a3.x = fmaf(wv.x, e3, a3.x); a3.y = fmaf(wv.y, e3, a3.y);
            a3.z = fmaf(wv.z, e3, a3.z); a3.w = fmaf(wv.w, e3, a3.w);
        }
        int s0 = pass * 32 + sb;
        float4 as[4] = {a0, a1, a2, a3};
#pragma unroll
        for (int ss = 0; ss < 4; ss++) {
            int s = s0 + ss;
            if (jt < 8)
                *(float4*)&g_gpre[(b * Ss + s) * G4 + jt * 128 + j4] = as[ss];
            else
                *(float4*)&g_eproj[(b * Ss + s) * Dd + (jt - 8) * 128 + j4] = as[ss];
        }
    }
}

// ---------------- decode: 8 clusters x 8 CTAs, 8 batches/cluster ------------
// Rank r owns: gate slice j' in [r*128, r*128+128) (= dims [r*32, r*32+32) of
// all 4 gates), q dims [r*32, r*32+32), and batch (cluster*8 + r) for argmax.
// Weight slices (128KB + 32KB) L1-resident after step 0. h exchanged via DSMEM
// pushes into a DOUBLE-BUFFERED H (by step parity): the h(N) push targets
// buf[N&1] while peers' phase A still reads buf[(N&1)^1] -> no WAR race, and
// existing cluster syncs separate buf reuse across N / N+2.
#define H_OFF    0        // [2 parity][256 k][8 b]
#define CST_OFF  4096     // [8 b][32 jj]
#define QS_OFF   4352     // [8 b][32 j]
#define GAT_OFF  4608     // [128 j'][8 b]
#define SCR_OFF  5632     // 4096: phase A partials [4 kq][128 j][8 b] / phase D [16 kq][32 j][8 b]
#define RECV_OFF 9728     // [8 rank][16 job] score partials
#define DEC_SMEM_FLOATS (9728 + 128)

__global__ void __launch_bounds__(512, 1) __cluster_dims__(CLU, 1, 1)
dec_k(const float* __restrict__ W2, const float* __restrict__ b2,
      float* __restrict__ out) {
    extern __shared__ float sm[];
    float* Hbuf = sm + H_OFF;            // two 2048-float H buffers
    float* cst  = sm + CST_OFF;
    float* qs   = sm + QS_OFF;
    float* gat  = sm + GAT_OFF;
    float* scr  = sm + SCR_OFF;
    float* recv = sm + RECV_OFF;
    __shared__ int next_t[128];          // [8 b][16 job]
    __shared__ int chosen_post;          // this CTA's owned-batch choice
    __shared__ const float* rowp[8];     // per local batch: gates premix row

    int t = threadIdx.x;
    int lane = t & 31, w = t >> 5;
    uint32_t r = ctarank();
    int bg_base = (blockIdx.x >> 3) * CLU;      // first global batch of cluster

    uint32_t H_u32 = smem_u32(Hbuf);
    uint32_t recv_u32 = smem_u32(recv);
    uint32_t chosen_u32 = smem_u32(&chosen_post);

    // init (both H parities zeroed; step 0 reads parity 1 = h(-1) = 0)
    for (int i = t; i < 4096; i += 512) Hbuf[i] = 0.f;
    if (t < 256) cst[t] = 0.f;
    if (t < 128) next_t[t] = 0;
    if (t < 8) rowp[t] = g_g0 + (size_t)(bg_base + t) * G4;
    float w2r = W2[r * 32 + lane];   // this rank's d-strip of W2, per lane
    float b2v = b2[0];
    __syncthreads();
    CLUSTER_SYNC();   // all inits complete before any peer pushes

    const float* whh = g_WhhT + r * 128;    // column base of rank slice
    const float* wq  = g_WqT + r * 32;

    for (int step = 0; step < Ss; step++) {
        int par = step & 1;
        float* Hcur  = Hbuf + par * 2048;        // h(step): written this step
        float* Hprev = Hbuf + (par ^ 1) * 2048;  // h(step-1): read in phase A

        // ---- phase A: gates partials from h(step-1). (j = t&127, kq = t>>7)
        {
            int j = t & 127, kq = t >> 7;
            int k0 = kq * 64;
            uint64_t a0 = 0, a1 = 0, a2 = 0, a3 = 0;   // b01,b23,b45,b67
#pragma unroll 8
            for (int k = k0; k < k0 + 64; k++) {
                float wv = whh[k * G4 + j];
                ulonglong2 ha = *(const ulonglong2*)&Hprev[k * 8];
                ulonglong2 hb = *(const ulonglong2*)&Hprev[k * 8 + 4];
                uint64_t ws = packsplat(wv);
                ffma2(a0, ws, ha.x); ffma2(a1, ws, ha.y);
                ffma2(a2, ws, hb.x); ffma2(a3, ws, hb.y);
            }
            ulonglong2* d0 = (ulonglong2*)&scr[kq * 1024 + j * 8];
            ulonglong2* d1 = (ulonglong2*)&scr[kq * 1024 + j * 8 + 4];
            d0->x = a0; d0->y = a1;
            d1->x = a2; d1->y = a3;
        }
        __syncthreads();
        // reduce 4 k-partials + add gates premix (gpre/g0, permuted slice)
        {
            int j = t >> 2, bp = (t & 3) * 2;
            uint64_t s = 0;
#pragma unroll
            for (int kq = 0; kq < 4; kq++) {
                uint64_t v = *(const uint64_t*)&scr[kq * 1024 + j * 8 + bp];
                ffma2(s, v, 0x3f8000003f800000ull);  // s += v * 1.0 (packed add)
            }
            float g0v = rowp[bp][r * 128 + j];
            float g1v = rowp[bp + 1][r * 128 + j];
            gat[j * 8 + bp] = lo2(s) + g0v;
            gat[j * 8 + bp + 1] = hi2(s) + g1v;
        }
        __syncthreads();

        // ---- phase B: LSTM pointwise for d-strip; write own rows of Hcur --
        if (t < 256) {
            int b = t >> 5, jj = t & 31;
            float ig = gat[jj * 8 + b];
            float fg = gat[(32 + jj) * 8 + b];
            float gg = gat[(64 + jj) * 8 + b];
            float og = gat[(96 + jj) * 8 + b];
            float cn = fsig(fg) * cst[b * 32 + jj] + fsig(ig) * ftanh(gg);
            cst[b * 32 + jj] = cn;
            Hcur[(r * 32 + jj) * 8 + b] = fsig(og) * ftanh(cn);
        }
        __syncthreads();
        // push own h strip (Hcur floats [r*256, r*256+256)) to peers' Hcur
        if (t < 64) {
            float4 v = *(const float4*)&Hcur[r * 256 + t * 4];
            uint32_t off = H_u32 + (par * 2048 + r * 256 + t * 4) * 4;
#pragma unroll
            for (int p = 0; p < CLU; p++)
                if (p != (int)r) stc_f4(mapa_u32(off, p), v);
        }
        CLUSTER_SYNC();   // sync 1: full h(step) everywhere in Hcur

        // ---- phase D: q partials from Hcur. (j = t&31, kq = t>>5) ----------
        {
            int j = t & 31, kq = t >> 5;
            int k0 = kq * 16;
            uint64_t a0 = 0, a1 = 0, a2 = 0, a3 = 0;
#pragma unroll
            for (int k = k0; k < k0 + 16; k++) {
                float wv = wq[k * Dd + j];
                ulonglong2 ha = *(const ulonglong2*)&Hcur[k * 8];
                ulonglong2 hb = *(const ulonglong2*)&Hcur[k * 8 + 4];
                uint64_t ws = packsplat(wv);
                ffma2(a0, ws, ha.x); ffma2(a1, ws, ha.y);
                ffma2(a2, ws, hb.x); ffma2(a3, ws, hb.y);
            }
            ulonglong2* d0 = (ulonglong2*)&scr[kq * 256 + j * 8];
            ulonglong2* d1 = (ulonglong2*)&scr[kq * 256 + j * 8 + 4];
            d0->x = a0; d0->y = a1;
            d1->x = a2; d1->y = a3;
        }
        __syncthreads();
        if (t < 128) {   // reduce 16 k-partials -> qs[b][32]
            int j = t >> 2, bp = (t & 3) * 2;
            uint64_t s = 0;
#pragma unroll
            for (int kq = 0; kq < 16; kq++) {
                uint64_t v = *(const uint64_t*)&scr[kq * 256 + j * 8 + bp];
                ffma2(s, v, 0x3f8000003f800000ull);
            }
            qs[bp * 32 + j] = lo2(s);
            qs[(bp + 1) * 32 + j] = hi2(s);
        }
        __syncthreads();

        // ---- phase E: attention partials over d-strip; push to owners -----
        // warp w: batch b = w>>1, jobs jg..jg+7 (jg = (w&1)*8). lane = local d.
        {
            int b = w >> 1, jg = (w & 1) * 8;
            int bg = bg_base + b;
            float q_l = qs[b * 32 + lane];
            float ev[8];
            int valid[8], scand[8];
#pragma unroll
            for (int j2 = 0; j2 < 8; j2++) {
                int j = jg + j2;
                int nx = next_t[b * 16 + j];
                valid[j2] = (nx < 8);
                scand[j2] = j * 8 + nx;
                ev[j2] = valid[j2]
                    ? __ldg(&g_eproj[((size_t)bg * Ss + scand[j2]) * Dd + r * 32 + lane])
                    : 0.f;
            }
#pragma unroll
            for (int j2 = 0; j2 < 8; j2++) {
                if (valid[j2]) {   // warp-uniform
                    float v = w2r * ftanh(ev[j2] + q_l);
#pragma unroll
                    for (int off = 16; off; off >>= 1)
                        v += __shfl_xor_sync(0xffffffffu, v, off);
                    if (lane == 0) {
                        // deliver partial to owner CTA (rank b), slot [r][job]
                        uint32_t dst = mapa_u32(recv_u32 + (r * 16 + jg + j2) * 4, b);
                        stc_f(dst, v);
                    }
                }
            }
        }
        CLUSTER_SYNC();   // sync 2: all partials delivered

        // ---- phase G: owner (this CTA's batch = bg_base + r) --------------
        if (t == 0) {
            float vals[16];
            float best = -3.4e38f;
            int bj = 0;
            for (int j = 0; j < 16; j++) {
                if (next_t[(int)r * 16 + j] < 8) {
                    float v = b2v;
#pragma unroll
                    for (int p = 0; p < CLU; p++) v += recv[p * 16 + j];
                    vals[j] = v;
                    if (v > best) { best = v; bj = j; }
                }
            }
            float sum = 0.f;
            for (int j = 0; j < 16; j++)
                if (next_t[(int)r * 16 + j] < 8) sum += __expf(vals[j] - best);
            int slot = bj * 8 + next_t[(int)r * 16 + bj];
            int bg = bg_base + (int)r;
            out[bg * Ss + step] = (float)slot;
            out[Bb * Ss + bg * Ss + step] = -__logf(sum);
            chosen_post = slot;
        }
        CLUSTER_SYNC();   // sync 3: chosen visible; recv safe to reuse

        // gather all 8 choices, update replicated state (skip on last step:
        // nothing left to compute, and the last cluster op stays sync 3)
        if (step < Ss - 1) {
            if (t < 8) {
                int ch = ldc_s32(mapa_u32(chosen_u32, (uint32_t)t));
                const float* row = g_gpre + ((size_t)(bg_base + t) * Ss + ch) * G4;
                rowp[t] = row;
                next_t[t * 16 + (ch >> 3)] += 1;
                // L2 prefetch hint: this rank's 512B slice of each premix row
                // (read cold by next step's phase-A reduce otherwise)
                prefetch_l2(row + r * 128);
                prefetch_l2(row + r * 128 + 32);
                prefetch_l2(row + r * 128 + 64);
                prefetch_l2(row + r * 128 + 96);
            }
            __syncthreads();
        }
    }
}

// ---------------- launcher ---------------------------------------------------
extern "C" void kernel_launch(void* const* d_in, const int* in_sizes, int n_in,
                              void* d_out, int out_size) {
    const float* enc  = (const float*)d_in[0];
    // d_in[1] = S_seq (deterministic job/op pattern, recomputed on device)
    const float* W_ih = (const float*)d_in[2];
    const float* W_hh = (const float*)d_in[3];
    const float* b_ih = (const float*)d_in[4];
    const float* b_hh = (const float*)d_in[5];
    const float* W1   = (const float*)d_in[6];
    const float* b1   = (const float*)d_in[7];
    const float* W2   = (const float*)d_in[8];
    const float* b2   = (const float*)d_in[9];
    float* out = (float*)d_out;

    cudaFuncSetAttribute(pre_k, cudaFuncAttributeMaxDynamicSharedMemorySize,
                         PRE_SMEM_FLOATS * 4);
    cudaFuncSetAttribute(dec_k, cudaFuncAttributeMaxDynamicSharedMemorySize,
                         DEC_SMEM_FLOATS * 4);

    prep_k<<<256, 256>>>(W_ih, W_hh, b_ih, b_hh, W1, b1);
    g0m_k<<<64, 256>>>(enc);
    pre_k<<<dim3(10, 64), 256, PRE_SMEM_FLOATS * 4>>>(enc);
    dec_k<<<64, 512, DEC_SMEM_FLOATS * 4>>>(W2, b2, out);
}

// round 15
// speedup vs baseline: 2.7695x; 1.0769x over previous
#include <cuda_runtime.h>
#include <math.h>
#include <stdint.h>

#define Dd 256
#define Ss 128
#define Bb 64
#define G4 1024     // 4*D
#define JTOT 1280   // 4*D (gates) + D (enc_proj)
#define CLU 8       // cluster size = ranks per cluster = batches per cluster

// ---------------- scratch (device globals; no allocation allowed) -------------
__device__ float g_WcatT[Dd * JTOT];     // [k][j] j<1024: W_ih^T (PERMUTED cols); j>=1024: We^T
__device__ float g_bcat[JTOT];           // b_ih+b_hh (PERMUTED, j<1024) ; b1
__device__ float g_WhhT[Dd * G4];        // [k][j PERMUTED]
__device__ float g_WqT[Dd * Dd];         // [k][j] natural order
__device__ float g_gpre[Bb * Ss * G4];   // permuted-j gate premix
__device__ float g_eproj[Bb * Ss * Dd];  // enc@We^T + b1 (natural d order)
__device__ float g_g0[Bb * G4];          // permuted-j gates for dec_h0

// Gate-column permutation: rank r owns contiguous 128-wide slice = dims
// [r*32, r*32+32) of all four gates; LSTM pointwise is rank-local.
__device__ __forceinline__ int permj(int j) {
    int g = j >> 8, d = j & 255;
    return ((d >> 5) << 7) + (g << 5) + (d & 31);
}

// Accurate transcendentals (MUFU.EX2/RCP based, ~5e-7 abs err).
__device__ __forceinline__ float fsig(float x) {
    return __fdividef(1.f, 1.f + __expf(-x));
}
__device__ __forceinline__ float ftanh(float x) {
    return 1.f - __fdividef(2.f, __expf(2.f * x) + 1.f);
}

// ---- packed f32x2 helpers (bit-exact IEEE fma per lane) ----
__device__ __forceinline__ uint64_t packsplat(float x) {
    uint64_t r;
    asm("mov.b64 %0, {%1, %1};" : "=l"(r) : "r"(__float_as_uint(x)));
    return r;
}
__device__ __forceinline__ void ffma2(uint64_t& acc, uint64_t a, uint64_t b) {
    asm("fma.rn.f32x2 %0, %1, %2, %0;" : "+l"(acc) : "l"(a), "l"(b));
}
__device__ __forceinline__ float lo2(uint64_t v) { return __uint_as_float((uint32_t)v); }
__device__ __forceinline__ float hi2(uint64_t v) { return __uint_as_float((uint32_t)(v >> 32)); }

// ---- cluster / DSMEM helpers ----
__device__ __forceinline__ uint32_t smem_u32(const void* p) {
    uint32_t a;
    asm("{ .reg .u64 t; cvta.to.shared.u64 t, %1; cvt.u32.u64 %0, t; }" : "=r"(a) : "l"(p));
    return a;
}
__device__ __forceinline__ uint32_t ctarank() {
    uint32_t r; asm("mov.u32 %0, %%cluster_ctarank;" : "=r"(r)); return r;
}
__device__ __forceinline__ uint32_t mapa_u32(uint32_t local, uint32_t rank) {
    uint32_t r; asm("mapa.shared::cluster.u32 %0, %1, %2;" : "=r"(r) : "r"(local), "r"(rank));
    return r;
}
__device__ __forceinline__ void stc_f4(uint32_t a, float4 v) {
    asm volatile("st.shared::cluster.v4.f32 [%0], {%1,%2,%3,%4};"
                 :: "r"(a), "f"(v.x), "f"(v.y), "f"(v.z), "f"(v.w) : "memory");
}
__device__ __forceinline__ void stc_f(uint32_t a, float v) {
    asm volatile("st.shared::cluster.f32 [%0], %1;" :: "r"(a), "f"(v) : "memory");
}
__device__ __forceinline__ void prefetch_l2(const void* p) {
    asm volatile("prefetch.global.L2 [%0];" :: "l"(p));
}
#define CLUSTER_SYNC() do { \
    asm volatile("barrier.cluster.arrive.aligned;" ::: "memory"); \
    asm volatile("barrier.cluster.wait.aligned;" ::: "memory"); \
} while (0)

// ---------------- weight prep: transposes + permutation + bias folding -------
__global__ void prep_k(const float* __restrict__ W_ih, const float* __restrict__ W_hh,
                       const float* __restrict__ b_ih, const float* __restrict__ b_hh,
                       const float* __restrict__ W1, const float* __restrict__ b1) {
    int i0 = blockIdx.x * blockDim.x + threadIdx.x;
    int stride = gridDim.x * blockDim.x;
    for (int idx = i0; idx < Dd * JTOT; idx += stride) {
        int k = idx / JTOT, j = idx - k * JTOT;
        if (j < G4)
            g_WcatT[k * JTOT + permj(j)] = W_ih[j * Dd + k];
        else
            g_WcatT[idx] = W1[(j - G4) * 512 + 256 + k];
    }
    for (int idx = i0; idx < Dd * G4; idx += stride) {
        int k = idx >> 10, j = idx & 1023;
        g_WhhT[k * G4 + permj(j)] = W_hh[j * Dd + k];
    }
    for (int idx = i0; idx < Dd * Dd; idx += stride) {
        int k = idx >> 8, j = idx & 255;
        g_WqT[idx] = W1[j * 512 + k];
    }
    if (i0 < JTOT) {
        float v = (i0 < G4) ? b_ih[i0] + b_hh[i0] : b1[i0 - G4];
        g_bcat[(i0 < G4) ? permj(i0) : i0] = v;
    }
}

// ------- dec_h0 = mean over s, then gates0 = dec_h0 @ W_ih^T + biases -------
__global__ void __launch_bounds__(256) g0m_k(const float* __restrict__ enc) {
    __shared__ float h[Dd];
    int b = blockIdx.x, t = threadIdx.x;
    {
        const float* p = enc + b * Ss * Dd + t;
        float s = 0.f;
#pragma unroll 8
        for (int ss = 0; ss < Ss; ss++) s += p[ss * Dd];
        h[t] = s * (1.0f / 128.0f);
    }
    __syncthreads();
    int j4 = t * 4;
    float4 acc = *(const float4*)&g_bcat[j4];
#pragma unroll 8
    for (int k = 0; k < Dd; k++) {
        float4 w = *(const float4*)&g_WcatT[k * JTOT + j4];
        float hk = h[k];
        acc.x = fmaf(w.x, hk, acc.x);
        acc.y = fmaf(w.y, hk, acc.y);
        acc.z = fmaf(w.z, hk, acc.z);
        acc.w = fmaf(w.w, hk, acc.w);
    }
    *(float4*)&g_g0[b * G4 + j4] = acc;
}

// ---------------- big precompute: gates_pre (permuted) + enc_proj -----------
#define PRE_SMEM_FLOATS (32768 + 8192 + 128)
__global__ void __launch_bounds__(256) pre_k(const float* __restrict__ enc) {
    extern __shared__ float sm[];
    float* Wt = sm;                // [256][128]
    float* encs = sm + 32768;      // [32][256]
    float* bt = sm + 32768 + 8192; // [128]
    int b = blockIdx.y, jt = blockIdx.x, t = threadIdx.x;
    int J0 = jt * 128;
    for (int idx = t; idx < 32768; idx += 256) {
        int k = idx >> 7, jj = idx & 127;
        Wt[idx] = g_WcatT[k * JTOT + J0 + jj];
    }
    if (t < 128) bt[t] = g_bcat[J0 + t];
    int lane = t & 31, w = t >> 5;
    int j4 = lane * 4;
    int sb = w * 4;
    for (int pass = 0; pass < 4; pass++) {
        __syncthreads();
        for (int idx = t; idx < 32 * 256; idx += 256)
            encs[idx] = enc[b * Ss * Dd + pass * 32 * Dd + idx];
        __syncthreads();
        float4 bb = *(const float4*)&bt[j4];
        float4 a0 = bb, a1 = bb, a2 = bb, a3 = bb;
#pragma unroll 4
        for (int k = 0; k < Dd; k++) {
            float4 wv = *(const float4*)&Wt[k * 128 + j4];
            float e0 = encs[(sb + 0) * 256 + k];
            float e1 = encs[(sb + 1) * 256 + k];
            float e2 = encs[(sb + 2) * 256 + k];
            float e3 = encs[(sb + 3) * 256 + k];
            a0.x = fmaf(wv.x, e0, a0.x); a0.y = fmaf(wv.y, e0, a0.y);
            a0.z = fmaf(wv.z, e0, a0.z); a0.w = fmaf(wv.w, e0, a0.w);
            a1.x = fmaf(wv.x, e1, a1.x); a1.y = fmaf(wv.y, e1, a1.y);
            a1.z = fmaf(wv.z, e1, a1.z); a1.w = fmaf(wv.w, e1, a1.w);
            a2.x = fmaf(wv.x, e2, a2.x); a2.y = fmaf(wv.y, e2, a2.y);
            a2.z = fmaf(wv.z, e2, a2.z); a2.w = fmaf(wv.w, e2, a2.w);
            a3.x = fmaf(wv.x, e3, a3.x); a3.y = fmaf(wv.y, e3, a3.y);
            a3.z = fmaf(wv.z, e3, a3.z); a3.w = fmaf(wv.w, e3, a3.w);
        }
        int s0 = pass * 32 + sb;
        float4 as[4] = {a0, a1, a2, a3};
#pragma unroll
        for (int ss = 0; ss < 4; ss++) {
            int s = s0 + ss;
            if (jt < 8)
                *(float4*)&g_gpre[(b * Ss + s) * G4 + jt * 128 + j4] = as[ss];
            else
                *(float4*)&g_eproj[(b * Ss + s) * Dd + (jt - 8) * 128 + j4] = as[ss];
        }
    }
}

// ---------------- decode: 8 clusters x 8 CTAs, 8 batches/cluster ------------
// v2: weight slices PINNED IN SMEM (immune to L1 policy, LDS-issue instead of
// LDG); 2 cluster syncs/step (score partials broadcast to ALL CTAs via
// lane-parallel DSMEM stores; argmax computed replicated+parallel, bitwise
// identical across CTAs -> no choice gather).
#define WHH_OFF  0                       // [256 k][128 j'] rank slice, 32768
#define WQ_OFF   32768                   // [256 k][32 j]  rank slice, 8192
#define H_OFF    (32768 + 8192)          // [2 parity][256 k][8 b], 4096
#define CST_OFF  (H_OFF + 4096)          // [8 b][32 jj], 256
#define QS_OFF   (CST_OFF + 256)         // [8 b][32 j], 256
#define GAT_OFF  (QS_OFF + 256)          // [128 j'][8 b], 1024
#define SCR_OFF  (GAT_OFF + 1024)        // 4096 partial scratch
#define RECV_OFF (SCR_OFF + 4096)        // [8 batch][8 rank][16 job], 1024
#define DEC_SMEM_FLOATS (RECV_OFF + 1024)

__global__ void __launch_bounds__(512, 1) __cluster_dims__(CLU, 1, 1)
dec_k(const float* __restrict__ W2, const float* __restrict__ b2,
      float* __restrict__ out) {
    extern __shared__ float sm[];
    float* whhs = sm + WHH_OFF;
    float* wqs  = sm + WQ_OFF;
    float* Hbuf = sm + H_OFF;
    float* cst  = sm + CST_OFF;
    float* qs   = sm + QS_OFF;
    float* gat  = sm + GAT_OFF;
    float* scr  = sm + SCR_OFF;
    float* recv = sm + RECV_OFF;
    __shared__ int next_t[128];          // [8 b][16 job], replicated
    __shared__ const float* rowp[8];     // per local batch: gates premix row

    int t = threadIdx.x;
    int lane = t & 31, w = t >> 5;
    uint32_t r = ctarank();
    int bg_base = (blockIdx.x >> 3) * CLU;

    uint32_t H_u32 = smem_u32(Hbuf);
    uint32_t recv_u32 = smem_u32(recv);

    // ---- load rank weight slices into smem (one-time) ----
    for (int i = t; i < 32768; i += 512) {        // whh slice [k][128]
        int k = i >> 7, j = i & 127;
        whhs[i] = g_WhhT[k * G4 + (int)r * 128 + j];
    }
    for (int i = t; i < 8192; i += 512) {         // wq slice [k][32]
        int k = i >> 5, j = i & 31;
        wqs[i] = g_WqT[k * Dd + (int)r * 32 + j];
    }
    for (int i = t; i < 4096; i += 512) Hbuf[i] = 0.f;
    if (t < 256) cst[t] = 0.f;
    if (t < 128) next_t[t] = 0;
    if (t < 8) rowp[t] = g_g0 + (size_t)(bg_base + t) * G4;
    float w2r = W2[r * 32 + lane];
    float b2v = b2[0];
    __syncthreads();
    CLUSTER_SYNC();   // all inits complete before any peer pushes

    for (int step = 0; step < Ss; step++) {
        int par = step & 1;
        float* Hcur  = Hbuf + par * 2048;
        float* Hprev = Hbuf + (par ^ 1) * 2048;

        // ---- phase A: gates partials from h(step-1). (j = t&127, kq = t>>7)
        {
            int j = t & 127, kq = t >> 7;
            int k0 = kq * 64;
            uint64_t a0 = 0, a1 = 0, a2 = 0, a3 = 0;   // b01,b23,b45,b67
#pragma unroll 8
            for (int k = k0; k < k0 + 64; k++) {
                float wv = whhs[k * 128 + j];          // LDS, conflict-free
                ulonglong2 ha = *(const ulonglong2*)&Hprev[k * 8];
                ulonglong2 hb = *(const ulonglong2*)&Hprev[k * 8 + 4];
                uint64_t ws = packsplat(wv);
                ffma2(a0, ws, ha.x); ffma2(a1, ws, ha.y);
                ffma2(a2, ws, hb.x); ffma2(a3, ws, hb.y);
            }
            ulonglong2* d0 = (ulonglong2*)&scr[kq * 1024 + j * 8];
            ulonglong2* d1 = (ulonglong2*)&scr[kq * 1024 + j * 8 + 4];
            d0->x = a0; d0->y = a1;
            d1->x = a2; d1->y = a3;
        }
        __syncthreads();
        // reduce 4 k-partials + add gates premix (gpre/g0, permuted slice)
        {
            int j = t >> 2, bp = (t & 3) * 2;
            uint64_t s = 0;
#pragma unroll
            for (int kq = 0; kq < 4; kq++) {
                uint64_t v = *(const uint64_t*)&scr[kq * 1024 + j * 8 + bp];
                ffma2(s, v, 0x3f8000003f800000ull);
            }
            float g0v = rowp[bp][r * 128 + j];
            float g1v = rowp[bp + 1][r * 128 + j];
            gat[j * 8 + bp] = lo2(s) + g0v;
            gat[j * 8 + bp + 1] = hi2(s) + g1v;
        }
        __syncthreads();

        // ---- phase B: LSTM pointwise for d-strip; write own rows of Hcur --
        if (t < 256) {
            int b = t >> 5, jj = t & 31;
            float ig = gat[jj * 8 + b];
            float fg = gat[(32 + jj) * 8 + b];
            float gg = gat[(64 + jj) * 8 + b];
            float og = gat[(96 + jj) * 8 + b];
            float cn = fsig(fg) * cst[b * 32 + jj] + fsig(ig) * ftanh(gg);
            cst[b * 32 + jj] = cn;
            Hcur[(r * 32 + jj) * 8 + b] = fsig(og) * ftanh(cn);
        }
        __syncthreads();
        // push own h strip to peers' Hcur
        if (t < 64) {
            float4 v = *(const float4*)&Hcur[r * 256 + t * 4];
            uint32_t off = H_u32 + (par * 2048 + r * 256 + t * 4) * 4;
#pragma unroll
            for (int p = 0; p < CLU; p++)
                if (p != (int)r) stc_f4(mapa_u32(off, p), v);
        }
        CLUSTER_SYNC();   // sync 1: full h(step) everywhere

        // ---- phase D: q partials from Hcur. (j = t&31, kq = t>>5) ----------
        {
            int j = t & 31, kq = t >> 5;
            int k0 = kq * 16;
            uint64_t a0 = 0, a1 = 0, a2 = 0, a3 = 0;
#pragma unroll
            for (int k = k0; k < k0 + 16; k++) {
                float wv = wqs[k * 32 + j];            // LDS, conflict-free
                ulonglong2 ha = *(const ulonglong2*)&Hcur[k * 8];
                ulonglong2 hb = *(const ulonglong2*)&Hcur[k * 8 + 4];
                uint64_t ws = packsplat(wv);
                ffma2(a0, ws, ha.x); ffma2(a1, ws, ha.y);
                ffma2(a2, ws, hb.x); ffma2(a3, ws, hb.y);
            }
            ulonglong2* d0 = (ulonglong2*)&scr[kq * 256 + j * 8];
            ulonglong2* d1 = (ulonglong2*)&scr[kq * 256 + j * 8 + 4];
            d0->x = a0; d0->y = a1;
            d1->x = a2; d1->y = a3;
        }
        __syncthreads();
        if (t < 128) {
            int j = t >> 2, bp = (t & 3) * 2;
            uint64_t s = 0;
#pragma unroll
            for (int kq = 0; kq < 16; kq++) {
                uint64_t v = *(const uint64_t*)&scr[kq * 256 + j * 8 + bp];
                ffma2(s, v, 0x3f8000003f800000ull);
            }
            qs[bp * 32 + j] = lo2(s);
            qs[(bp + 1) * 32 + j] = hi2(s);
        }
        __syncthreads();

        // ---- phase E: attention partials; BROADCAST to all 8 CTAs ---------
        // warp w: batch b = w>>1, jobs jg..jg+7. lane = local d. After the
        // bfly reduce every lane holds v; lanes 0..7 deliver to 8 CTAs.
        {
            int b = w >> 1, jg = (w & 1) * 8;
            int bg = bg_base + b;
            float q_l = qs[b * 32 + lane];
            float ev[8];
            int valid[8];
#pragma unroll
            for (int j2 = 0; j2 < 8; j2++) {
                int j = jg + j2;
                int nx = next_t[b * 16 + j];
                valid[j2] = (nx < 8);
                ev[j2] = valid[j2]
                    ? __ldg(&g_eproj[((size_t)bg * Ss + j * 8 + nx) * Dd + r * 32 + lane])
                    : 0.f;
            }
#pragma unroll
            for (int j2 = 0; j2 < 8; j2++) {
                if (valid[j2]) {   // warp-uniform
                    float v = w2r * ftanh(ev[j2] + q_l);
#pragma unroll
                    for (int off = 16; off; off >>= 1)
                        v += __shfl_xor_sync(0xffffffffu, v, off);
                    if (lane < CLU) {
                        uint32_t dst = mapa_u32(
                            recv_u32 + (b * 128 + (int)r * 16 + jg + j2) * 4,
                            (uint32_t)lane);
                        stc_f(dst, v);
                    }
                }
            }
        }
        CLUSTER_SYNC();   // sync 2: all partials everywhere

        // ---- phase G': replicated parallel argmax (thread t = batch t) ----
        // Fixed summation order -> bitwise-identical across CTAs.
        if (t < 8) {
            int b = t;
            float best = -3.4e38f;
            int bj = 0;
            float vals[16];
            for (int j = 0; j < 16; j++) {
                if (next_t[b * 16 + j] < 8) {
                    float v = b2v;
#pragma unroll
                    for (int p = 0; p < CLU; p++) v += recv[b * 128 + p * 16 + j];
                    vals[j] = v;
                    if (v > best) { best = v; bj = j; }
                }
            }
            float sum = 0.f;
            for (int j = 0; j < 16; j++)
                if (next_t[b * 16 + j] < 8) sum += __expf(vals[j] - best);
            int slot = bj * 8 + next_t[b * 16 + bj];
            if (b == (int)r) {   // owner writes output for its batch
                int bg = bg_base + b;
                out[bg * Ss + step] = (float)slot;
                out[Bb * Ss + bg * Ss + step] = -__logf(sum);
            }
            next_t[b * 16 + bj] += 1;
            const float* row = g_gpre + ((size_t)(bg_base + b) * Ss + slot) * G4;
            rowp[b] = row;
            prefetch_l2(row + r * 128);
            prefetch_l2(row + r * 128 + 32);
            prefetch_l2(row + r * 128 + 64);
            prefetch_l2(row + r * 128 + 96);
        }
        __syncthreads();
    }
}

// ---------------- launcher ---------------------------------------------------
extern "C" void kernel_launch(void* const* d_in, const int* in_sizes, int n_in,
                              void* d_out, int out_size) {
    const float* enc  = (const float*)d_in[0];
    // d_in[1] = S_seq (deterministic job/op pattern, recomputed on device)
    const float* W_ih = (const float*)d_in[2];
    const float* W_hh = (const float*)d_in[3];
    const float* b_ih = (const float*)d_in[4];
    const float* b_hh = (const float*)d_in[5];
    const float* W1   = (const float*)d_in[6];
    const float* b1   = (const float*)d_in[7];
    const float* W2   = (const float*)d_in[8];
    const float* b2   = (const float*)d_in[9];
    float* out = (float*)d_out;

    cudaFuncSetAttribute(pre_k, cudaFuncAttributeMaxDynamicSharedMemorySize,
                         PRE_SMEM_FLOATS * 4);
    cudaFuncSetAttribute(dec_k, cudaFuncAttributeMaxDynamicSharedMemorySize,
                         DEC_SMEM_FLOATS * 4);

    prep_k<<<256, 256>>>(W_ih, W_hh, b_ih, b_hh, W1, b1);
    g0m_k<<<64, 256>>>(enc);
    pre_k<<<dim3(10, 64), 256, PRE_SMEM_FLOATS * 4>>>(enc);
    dec_k<<<64, 512, DEC_SMEM_FLOATS * 4>>>(W2, b2, out);
}